// round 15
// baseline (speedup 1.0000x reference)
#include <cuda_runtime.h>
#include <cuda_fp16.h>
#include <math.h>
#include <float.h>
#include <stdint.h>

// Problem constants
#define BATCH 32
#define LSEQ  2048
#define EDIM  1024
#define NHEAD 16
#define DHEAD 64
#define HD    (NHEAD * DHEAD)     // 1024
#define ROWS  (BATCH * LSEQ)      // 65536
#define FLAT  (LSEQ * EDIM)       // 2097152
#define NCLS  2

// fp8 scaling: inputs scaled by 32 before e4m3 quantization; products carry
// 32*32 = 1024; epilogue descales by 2^-10.
#define FP8_SCALE   32.0f
#define INV_SCALE   0.03125f          // 1/32
#define DESCALE     9.765625e-4f      // 1/1024

#define SMEM_SWIZZLE_128B(byte_offset) \
    ((byte_offset) ^ (((byte_offset) >> 3) & 0x70))

__device__ __forceinline__ uint32_t smem_to_u32(const void* smem_ptr) {
    uint32_t addr;
    asm("{ .reg .u64 tmp; cvta.to.shared.u64 tmp, %1; cvt.u32.u64 %0, tmp; }"
        : "=r"(addr) : "l"(smem_ptr));
    return addr;
}

__device__ __forceinline__ void cp_async16(uint32_t smem_addr, const void* gptr) {
    asm volatile("cp.async.cg.shared.global [%0], [%1], 16;"
                 :: "r"(smem_addr), "l"(gptr) : "memory");
}
__device__ __forceinline__ void cp_commit() {
    asm volatile("cp.async.commit_group;" ::: "memory");
}

__device__ __forceinline__ void ldmx4(uint32_t* r, uint32_t addr) {
    asm volatile("ldmatrix.sync.aligned.m8n8.x4.shared.b16 {%0,%1,%2,%3}, [%4];"
                 : "=r"(r[0]), "=r"(r[1]), "=r"(r[2]), "=r"(r[3]) : "r"(addr));
}
__device__ __forceinline__ void ldmx4t(uint32_t* r, uint32_t addr) {
    asm volatile("ldmatrix.sync.aligned.m8n8.x4.trans.shared.b16 {%0,%1,%2,%3}, [%4];"
                 : "=r"(r[0]), "=r"(r[1]), "=r"(r[2]), "=r"(r[3]) : "r"(addr));
}

// fp8 e4m3 inputs, f16 accumulator (legacy QMMA path; k32 fragment byte
// layout matches f16 k16, so ldmatrix addressing is reused verbatim)
__device__ __forceinline__ void mma16832q(uint32_t* c, const uint32_t* a, const uint32_t* b) {
    asm volatile(
        "mma.sync.aligned.m16n8k32.row.col.f16.e4m3.e4m3.f16 "
        "{%0,%1}, {%2,%3,%4,%5}, {%6,%7}, {%0,%1};"
        : "+r"(c[0]), "+r"(c[1])
        : "r"(a[0]), "r"(a[1]), "r"(a[2]), "r"(a[3]), "r"(b[0]), "r"(b[1]));
}

// f16 inputs, f32 accumulator (attention)
__device__ __forceinline__ void mma16816f(float* c, const uint32_t* a, const uint32_t* b) {
    asm volatile(
        "mma.sync.aligned.m16n8k16.row.col.f32.f16.f16.f32 "
        "{%0,%1,%2,%3}, {%4,%5,%6,%7}, {%8,%9}, {%0,%1,%2,%3};"
        : "+f"(c[0]), "+f"(c[1]), "+f"(c[2]), "+f"(c[3])
        : "r"(a[0]), "r"(a[1]), "r"(a[2]), "r"(a[3]), "r"(b[0]), "r"(b[1]));
}

// ---- fp8 pack/unpack helpers (baseline PTX cvt, sm_89+) ----
__device__ __forceinline__ uint16_t pack_fp8x2(float lo, float hi) {
    uint16_t r;
    asm("cvt.rn.satfinite.e4m3x2.f32 %0, %1, %2;" : "=h"(r) : "f"(hi), "f"(lo));
    return r;
}
__device__ __forceinline__ uint32_t pack_fp8x4(float a, float b, float c, float d) {
    uint16_t lo = pack_fp8x2(a, b);
    uint16_t hi = pack_fp8x2(c, d);
    return (uint32_t)lo | ((uint32_t)hi << 16);
}
__device__ __forceinline__ float2 fp8x2_to_float2(uint16_t v) {
    uint32_t h2;
    asm("cvt.rn.f16x2.e4m3x2 %0, %1;" : "=r"(h2) : "h"(v));
    return __half22float2(*(__half2*)&h2);
}

// ---------------------------------------------------------------------------
// Device-global scratch
// ---------------------------------------------------------------------------
__device__ unsigned char g_h8[(size_t)ROWS * EDIM];       // 64 MB fp8(h*32)
__device__ __half g_qb[(size_t)ROWS * HD];                // q (f16)
__device__ __half g_kb[(size_t)ROWS * HD];
__device__ __half g_vb[(size_t)ROWS * HD];
__device__ unsigned char g_att8[(size_t)ROWS * HD];       // 64 MB fp8(att*32)
__device__ unsigned char g_w8qkv[(size_t)3 * HD * EDIM];  // fp8(W^T*32)
__device__ unsigned char g_w8o[(size_t)EDIM * HD];
__device__ __half g_wf16[(size_t)FLAT * NCLS];            // 8 MB f16 Wf
__device__ double g_logits[BATCH * NCLS];

// ---------------------------------------------------------------------------
// 1) MERGED prologue: weight transposes -> fp8 (+logits zero), Wf -> f16,
//    and embedding gather -> fp8, one launch.
// ---------------------------------------------------------------------------
#define TRANS_BLOCKS 4096          // 32 x 32 x 4
#define WF_BLOCKS    2048
#define PREP_BLOCKS  (TRANS_BLOCKS + WF_BLOCKS + ROWS)

__global__ __launch_bounds__(256) void prep_kernel(
    const int* __restrict__ x, const float* __restrict__ emb,
    const float* __restrict__ Wq, const float* __restrict__ Wkv,
    const float* __restrict__ Wo, const float* __restrict__ Wf)
{
    __shared__ float tile[32][33];
    int bid = blockIdx.x;

    if (bid < TRANS_BLOCKS) {
        // ---- weight transpose + fp8 convert (scaled by 32) ----
        int z  = bid >> 10;
        int zi = bid & 1023;
        int bx = (zi & 31) * 32;     // n block
        int by = (zi >> 5) * 32;     // k block

        if (bid == 0 && threadIdx.x < BATCH * NCLS)
            g_logits[threadIdx.x] = 0.0;

        const float* in; int ldin, coloff; unsigned char* out;
        switch (z) {
            case 0: in = Wq;  ldin = HD;     coloff = 0;  out = g_w8qkv;                          break;
            case 1: in = Wkv; ldin = 2 * HD; coloff = 0;  out = g_w8qkv + (size_t)HD * EDIM;      break;
            case 2: in = Wkv; ldin = 2 * HD; coloff = HD; out = g_w8qkv + (size_t)2 * HD * EDIM;  break;
            default: in = Wo; ldin = EDIM;   coloff = 0;  out = g_w8o;                            break;
        }
        int tx = threadIdx.x & 31;
        int ty = threadIdx.x >> 5;
        for (int i = ty; i < 32; i += 8)
            tile[i][tx] = in[(size_t)(by + i) * ldin + coloff + bx + tx];
        __syncthreads();
        for (int i = ty; i < 32; i += 8) {
            uint16_t p = pack_fp8x2(tile[tx][i] * FP8_SCALE, 0.f);
            out[(size_t)(bx + i) * 1024 + by + tx] = (unsigned char)p;
        }
    } else if (bid < TRANS_BLOCKS + WF_BLOCKS) {
        // ---- Wf f32 -> f16 ----
        size_t base = (size_t)(bid - TRANS_BLOCKS) * 2048 + (size_t)threadIdx.x * 8;
        float4 f0 = *(const float4*)(Wf + base);
        float4 f1 = *(const float4*)(Wf + base + 4);
        __half2 h0 = __floats2half2_rn(f0.x, f0.y);
        __half2 h1 = __floats2half2_rn(f0.z, f0.w);
        __half2 h2 = __floats2half2_rn(f1.x, f1.y);
        __half2 h3 = __floats2half2_rn(f1.z, f1.w);
        uint4 o;
        o.x = *(uint32_t*)&h0; o.y = *(uint32_t*)&h1;
        o.z = *(uint32_t*)&h2; o.w = *(uint32_t*)&h3;
        *(uint4*)(g_wf16 + base) = o;
    } else {
        // ---- embedding gather -> fp8 (scaled by 32) ----
        int row = bid - TRANS_BLOCKS - WF_BLOCKS;
        int v = x[row];
        int t = threadIdx.x;
        float4 f = ((const float4*)(emb + (size_t)v * EDIM))[t];
        uint32_t p = pack_fp8x4(f.x * FP8_SCALE, f.y * FP8_SCALE,
                                f.z * FP8_SCALE, f.w * FP8_SCALE);
        ((uint32_t*)(g_h8 + (size_t)row * 1024))[t] = p;
    }
}

// ---------------------------------------------------------------------------
// 2) fp8 tensor-core GEMM (128x128, 256 thr, 3-stage, 2 CTA/SM).
//    K = 1024 fp8 = 8 chunks of 128 B (vs 16 for f16): MMA count halves.
//    Fragment byte layout identical to the f16 kernel -> same ldmatrix code.
//    LOGITS variant: epilogue adds fp8 residual, dots with f16 Wf,
//    per-warp atomics. Raster unchanged from R12/R14.
// ---------------------------------------------------------------------------
#define MT 128
#define NT 128
#define A_BYTES (MT * 128)          // 16 KB per K-chunk of 128 fp8
#define B_BYTES (NT * 128)
#define NCHUNKS 8
#define STAGES 3
#define GEMM_SMEM (STAGES * (A_BYTES + B_BYTES) + 1024)   // 99328

__device__ __forceinline__ void load_chunk(
    uint32_t abuf, uint32_t bbuf,
    const char* Abase, const char* Bbase, int c, int t)
{
#pragma unroll
    for (int i = 0; i < 4; i++) {
        int seg = t + 256 * i;
        int r = seg >> 3, s = seg & 7;
        uint32_t off = SMEM_SWIZZLE_128B((uint32_t)(r * 128 + s * 16));
        cp_async16(abuf + off, Abase + (size_t)r * 1024 + c * 128 + s * 16);
    }
#pragma unroll
    for (int i = 0; i < 4; i++) {
        int seg = t + 256 * i;
        int r = seg >> 3, s = seg & 7;
        uint32_t off = SMEM_SWIZZLE_128B((uint32_t)(r * 128 + s * 16));
        cp_async16(bbuf + off, Bbase + (size_t)r * 1024 + c * 128 + s * 16);
    }
}

template<bool LOGITS>
__global__ __launch_bounds__(256, 2) void gemm_fp8_kernel(
    const unsigned char* __restrict__ A,
    const unsigned char* __restrict__ Bt,
    const unsigned char* __restrict__ Res,
    __half* __restrict__ D0,
    __half* __restrict__ D1,
    __half* __restrict__ D2,
    int nxblocks)
{
    extern __shared__ char smem[];
    uint32_t base = (smem_to_u32(smem) + 1023) & ~1023u;
    uint32_t a_sm[STAGES], b_sm[STAGES];
#pragma unroll
    for (int s = 0; s < STAGES; s++) {
        a_sm[s] = base + s * (A_BYTES + B_BYTES);
        b_sm[s] = a_sm[s] + A_BYTES;
    }

    int t = threadIdx.x;
    int wid = t >> 5, lane = t & 31;
    int mwarp0 = (wid & 3) * 32;
    int nwarp0 = (wid >> 2) * 64;

    int bid = blockIdx.x;
    int bx, by;
    if (LOGITS) {
        int b    = bid & 31;
        bx       = (bid >> 5) & 7;
        int lblk = bid >> 8;
        by = b * 16 + lblk;
    } else {
        int group = bid / (nxblocks * 8);
        int rem   = bid % (nxblocks * 8);
        bx = rem % nxblocks;
        by = group * 8 + (rem / nxblocks);
    }

    size_t row0 = (size_t)by * MT;
    int col0 = bx * NT;

    int tgt = col0 >> 10;
    int colc = col0 & 1023;
    __half* D = (tgt == 0) ? D0 : ((tgt == 1) ? D1 : D2);

    const char* Abase = (const char*)(A + row0 * 1024);
    const char* Bbase = (const char*)(Bt + (size_t)col0 * 1024);

    // per-lane ldmatrix address components (identical to f16 version)
    int g = lane & 7, sel = lane >> 3;
    int mA = mwarp0 + g + (sel & 1) * 8;
    uint32_t aRow[2] = { (uint32_t)(mA * 128), (uint32_t)((mA + 16) * 128) };
    uint32_t aKb = (uint32_t)((sel >> 1) * 16);
    uint32_t aX  = (uint32_t)((mA & 7) << 4);

    int nB = nwarp0 + g + ((sel >> 1) * 8);
    uint32_t bRow[4] = { (uint32_t)(nB * 128), (uint32_t)((nB + 16) * 128),
                         (uint32_t)((nB + 32) * 128), (uint32_t)((nB + 48) * 128) };
    uint32_t bKb = (uint32_t)((sel & 1) * 16);
    uint32_t bX  = (uint32_t)((nB & 7) << 4);

    uint32_t hacc[2][8][2];
#pragma unroll
    for (int i = 0; i < 2; i++)
#pragma unroll
        for (int j = 0; j < 8; j++) { hacc[i][j][0] = 0u; hacc[i][j][1] = 0u; }

    load_chunk(a_sm[0], b_sm[0], Abase, Bbase, 0, t); cp_commit();
    load_chunk(a_sm[1], b_sm[1], Abase, Bbase, 1, t); cp_commit();

#pragma unroll
    for (int c = 0; c < NCHUNKS; c++) {
        int stage = c % STAGES;
        if (c < NCHUNKS - 1) {
            asm volatile("cp.async.wait_group 1;" ::: "memory");
        } else {
            asm volatile("cp.async.wait_group 0;" ::: "memory");
        }
        __syncthreads();
        if (c + 2 < NCHUNKS) {
            int ns = (c + 2) % STAGES;
            load_chunk(a_sm[ns], b_sm[ns], Abase, Bbase, c + 2, t);
            cp_commit();
        }

        uint32_t ab = a_sm[stage], bb = b_sm[stage];
#pragma unroll
        for (int s = 0; s < 4; s++) {          // 4 k32 steps per 128B chunk
            uint32_t kb0 = (uint32_t)(s * 32);
            uint32_t afrag[2][4], bfrag[4][4];
#pragma unroll
            for (int mi = 0; mi < 2; mi++)
                ldmx4(afrag[mi], ab + aRow[mi] + ((aKb + kb0) ^ aX));
#pragma unroll
            for (int j = 0; j < 4; j++)
                ldmx4(bfrag[j], bb + bRow[j] + ((bKb + kb0) ^ bX));
#pragma unroll
            for (int mi = 0; mi < 2; mi++)
#pragma unroll
                for (int j = 0; j < 4; j++) {
                    mma16832q(hacc[mi][2 * j],     afrag[mi], &bfrag[j][0]);
                    mma16832q(hacc[mi][2 * j + 1], afrag[mi], &bfrag[j][2]);
                }
        }
    }

    if (!LOGITS) {
        // Epilogue: descale by 2^-10 and store f16 q/k/v
        const __half2 desc = __float2half2_rn(DESCALE);
#pragma unroll
        for (int mi = 0; mi < 2; mi++) {
            size_t r0 = row0 + mwarp0 + mi * 16 + (lane >> 2);
#pragma unroll
            for (int nj = 0; nj < 8; nj++) {
                int col = colc + nwarp0 + nj * 8 + (lane & 3) * 2;
                __half2 a0 = __hmul2(*(__half2*)&hacc[mi][nj][0], desc);
                __half2 a1 = __hmul2(*(__half2*)&hacc[mi][nj][1], desc);
                *(uint32_t*)(D + r0 * 1024 + col)       = *(uint32_t*)&a0;
                *(uint32_t*)(D + (r0 + 8) * 1024 + col) = *(uint32_t*)&a1;
            }
        }
    } else {
        // Fused-logits epilogue: out = acc/1024 + res/32; dot with f16 Wf.
        float a0 = 0.f, a1 = 0.f;
        int bidx = (int)(row0 >> 11);
#pragma unroll
        for (int mi = 0; mi < 2; mi++) {
            size_t r0 = row0 + mwarp0 + mi * 16 + (lane >> 2);
            int l0 = (int)(r0 & 2047);
#pragma unroll
            for (int nj = 0; nj < 8; nj++) {
                int col = colc + nwarp0 + nj * 8 + (lane & 3) * 2;
                float2 f0 = __half22float2(*(__half2*)&hacc[mi][nj][0]);
                float2 f1 = __half22float2(*(__half2*)&hacc[mi][nj][1]);
                float2 h0 = fp8x2_to_float2(*(const uint16_t*)(Res + r0 * 1024 + col));
                float2 h1 = fp8x2_to_float2(*(const uint16_t*)(Res + (r0 + 8) * 1024 + col));
                f0.x = f0.x * DESCALE + h0.x * INV_SCALE;
                f0.y = f0.y * DESCALE + h0.y * INV_SCALE;
                f1.x = f1.x * DESCALE + h1.x * INV_SCALE;
                f1.y = f1.y * DESCALE + h1.y * INV_SCALE;
                uint2 w0u = *(const uint2*)(g_wf16 + ((size_t)l0 * 1024 + col) * 2);
                uint2 w1u = *(const uint2*)(g_wf16 + ((size_t)(l0 + 8) * 1024 + col) * 2);
                float2 w00 = __half22float2(*(__half2*)&w0u.x);
                float2 w01 = __half22float2(*(__half2*)&w0u.y);
                float2 w10 = __half22float2(*(__half2*)&w1u.x);
                float2 w11 = __half22float2(*(__half2*)&w1u.y);
                a0 += f0.x * w00.x + f0.y * w01.x + f1.x * w10.x + f1.y * w11.x;
                a1 += f0.x * w00.y + f0.y * w01.y + f1.x * w10.y + f1.y * w11.y;
            }
        }
#pragma unroll
        for (int off = 16; off >= 1; off >>= 1) {
            a0 += __shfl_xor_sync(0xffffffffu, a0, off);
            a1 += __shfl_xor_sync(0xffffffffu, a1, off);
        }
        if (lane == 0) {
            atomicAdd(&g_logits[2 * bidx],     (double)a0);
            atomicAdd(&g_logits[2 * bidx + 1], (double)a1);
        }
    }
}

// ---------------------------------------------------------------------------
// 3) Attention on tensor cores (f16 in, f32 softmax accum, fp8 out).
// ---------------------------------------------------------------------------
#define ATT_WARPS 8
#define ATT_SMEM (ATT_WARPS * 3 * 4096)   // 96 KB
#define ROWSTRIDE_B (LSEQ * NHEAD * DHEAD * 2)  // f16 batch-row stride bytes
#define ROWSTRIDE_E (LSEQ * NHEAD * DHEAD)      // element batch-row stride

__global__ __launch_bounds__(256) void attn_kernel()
{
    extern __shared__ char asmem[];
    int t = threadIdx.x, w = t >> 5, lane = t & 31;
    uint32_t wbase = smem_to_u32(asmem) + w * 12288;
    uint32_t qsm = wbase, ksm = wbase + 4096, vsm = wbase + 8192;

    int pair = blockIdx.x * ATT_WARPS + w;
    int l = pair >> 4, n = pair & 15;
    size_t ebase = ((size_t)l * NHEAD + n) * DHEAD;
    const char* qg = (const char*)(g_qb + ebase);
    const char* kg = (const char*)(g_kb + ebase);
    const char* vg = (const char*)(g_vb + ebase);

#pragma unroll
    for (int i = 0; i < 8; i++) {
        int s = lane + 32 * i;
        int row = s >> 3, sub = s & 7;
        size_t go = (size_t)row * ROWSTRIDE_B + sub * 16;
        uint32_t so = SMEM_SWIZZLE_128B((uint32_t)(row * 128 + sub * 16));
        cp_async16(qsm + so, qg + go);
        cp_async16(ksm + so, kg + go);
        cp_async16(vsm + so, vg + go);
    }
    cp_commit();
    asm volatile("cp.async.wait_group 0;" ::: "memory");
    __syncwarp();

    int g8 = lane & 7, sel = lane >> 3;

    // ---- S = Q K^T ----
    float c[2][4][4];
#pragma unroll
    for (int mi = 0; mi < 2; mi++)
#pragma unroll
        for (int j = 0; j < 4; j++)
#pragma unroll
            for (int k = 0; k < 4; k++) c[mi][j][k] = 0.f;

#pragma unroll
    for (int kc = 0; kc < 4; kc++) {
        uint32_t kb = kc * 32;
        uint32_t af[2][4], bfr[2][4];
#pragma unroll
        for (int mi = 0; mi < 2; mi++) {
            int row = mi * 16 + g8 + (sel & 1) * 8;
            uint32_t off = row * 128 + ((kb + (sel >> 1) * 16) ^ ((row & 7) << 4));
            ldmx4(af[mi], qsm + off);
        }
#pragma unroll
        for (int nj2 = 0; nj2 < 2; nj2++) {
            int row = nj2 * 16 + g8 + (sel >> 1) * 8;
            uint32_t off = row * 128 + ((kb + (sel & 1) * 16) ^ ((row & 7) << 4));
            ldmx4(bfr[nj2], ksm + off);
        }
#pragma unroll
        for (int mi = 0; mi < 2; mi++)
#pragma unroll
            for (int nj2 = 0; nj2 < 2; nj2++) {
                mma16816f(c[mi][2 * nj2],     af[mi], &bfr[nj2][0]);
                mma16816f(c[mi][2 * nj2 + 1], af[mi], &bfr[nj2][2]);
            }
    }

    // ---- softmax ----
    float inv0[2], inv1[2];
#pragma unroll
    for (int mi = 0; mi < 2; mi++) {
        float m0 = -FLT_MAX, m1 = -FLT_MAX;
#pragma unroll
        for (int j = 0; j < 4; j++) {
#pragma unroll
            for (int k = 0; k < 4; k++) c[mi][j][k] *= 0.125f;
            m0 = fmaxf(m0, fmaxf(c[mi][j][0], c[mi][j][1]));
            m1 = fmaxf(m1, fmaxf(c[mi][j][2], c[mi][j][3]));
        }
        m0 = fmaxf(m0, __shfl_xor_sync(0xffffffffu, m0, 1));
        m0 = fmaxf(m0, __shfl_xor_sync(0xffffffffu, m0, 2));
        m1 = fmaxf(m1, __shfl_xor_sync(0xffffffffu, m1, 1));
        m1 = fmaxf(m1, __shfl_xor_sync(0xffffffffu, m1, 2));
        float s0 = 0.f, s1 = 0.f;
#pragma unroll
        for (int j = 0; j < 4; j++) {
            c[mi][j][0] = __expf(c[mi][j][0] - m0);
            c[mi][j][1] = __expf(c[mi][j][1] - m0);
            c[mi][j][2] = __expf(c[mi][j][2] - m1);
            c[mi][j][3] = __expf(c[mi][j][3] - m1);
            s0 += c[mi][j][0] + c[mi][j][1];
            s1 += c[mi][j][2] + c[mi][j][3];
        }
        s0 += __shfl_xor_sync(0xffffffffu, s0, 1);
        s0 += __shfl_xor_sync(0xffffffffu, s0, 2);
        s1 += __shfl_xor_sync(0xffffffffu, s1, 1);
        s1 += __shfl_xor_sync(0xffffffffu, s1, 2);
        inv0[mi] = 1.f / s0;
        inv1[mi] = 1.f / s1;
    }

    // ---- pack P ----
    uint32_t pf[2][2][4];
#pragma unroll
    for (int mi = 0; mi < 2; mi++)
#pragma unroll
        for (int kc = 0; kc < 2; kc++) {
            __half2 x0 = __floats2half2_rn(c[mi][2 * kc][0],     c[mi][2 * kc][1]);
            __half2 x1 = __floats2half2_rn(c[mi][2 * kc][2],     c[mi][2 * kc][3]);
            __half2 x2 = __floats2half2_rn(c[mi][2 * kc + 1][0], c[mi][2 * kc + 1][1]);
            __half2 x3 = __floats2half2_rn(c[mi][2 * kc + 1][2], c[mi][2 * kc + 1][3]);
            pf[mi][kc][0] = *(uint32_t*)&x0;
            pf[mi][kc][1] = *(uint32_t*)&x1;
            pf[mi][kc][2] = *(uint32_t*)&x2;
            pf[mi][kc][3] = *(uint32_t*)&x3;
        }

    // ---- att = P V ----
    float cv[2][8][4];
#pragma unroll
    for (int mi = 0; mi < 2; mi++)
#pragma unroll
        for (int j = 0; j < 8; j++)
#pragma unroll
            for (int k = 0; k < 4; k++) cv[mi][j][k] = 0.f;

#pragma unroll
    for (int kc = 0; kc < 2; kc++) {
#pragma unroll
        for (int dj2 = 0; dj2 < 4; dj2++) {
            int row = kc * 16 + g8 + (sel & 1) * 8;
            uint32_t colb = dj2 * 32 + (sel >> 1) * 16;
            uint32_t off = row * 128 + (colb ^ ((row & 7) << 4));
            uint32_t bv[4];
            ldmx4t(bv, vsm + off);
#pragma unroll
            for (int mi = 0; mi < 2; mi++) {
                mma16816f(cv[mi][2 * dj2],     pf[mi][kc], &bv[0]);
                mma16816f(cv[mi][2 * dj2 + 1], pf[mi][kc], &bv[2]);
            }
        }
    }

    // ---- normalize + store fp8 (scaled by 32) ----
    int r = lane >> 2, cq = (lane & 3) * 2;
#pragma unroll
    for (int mi = 0; mi < 2; mi++) {
        int i0 = mi * 16 + r;
        float sc0 = inv0[mi] * FP8_SCALE;
        float sc1 = inv1[mi] * FP8_SCALE;
        unsigned char* o0 = g_att8 + ebase + (size_t)i0 * ROWSTRIDE_E;
        unsigned char* o1 = o0 + (size_t)8 * ROWSTRIDE_E;
#pragma unroll
        for (int dj = 0; dj < 8; dj++) {
            int col = dj * 8 + cq;
            uint16_t p0 = pack_fp8x2(cv[mi][dj][0] * sc0, cv[mi][dj][1] * sc0);
            uint16_t p1 = pack_fp8x2(cv[mi][dj][2] * sc1, cv[mi][dj][3] * sc1);
            *(uint16_t*)(o0 + col) = p0;
            *(uint16_t*)(o1 + col) = p1;
        }
    }
}

// ---------------------------------------------------------------------------
// 4) Loss
// ---------------------------------------------------------------------------
__global__ void loss_kernel(const int* __restrict__ y,
                            const float* __restrict__ bf,
                            float* __restrict__ out)
{
    if (threadIdx.x != 0 || blockIdx.x != 0) return;
    double s = 0.0;
    double b0 = (double)bf[0], b1 = (double)bf[1];
    for (int b = 0; b < BATCH; b++) {
        double l0 = g_logits[2 * b]     + b0;
        double l1 = g_logits[2 * b + 1] + b1;
        double m  = l0 > l1 ? l0 : l1;
        double lse = m + log(exp(l0 - m) + exp(l1 - m));
        double lp  = (y[b] == 0 ? l0 : l1) - lse;
        s += lp;
    }
    out[0] = (float)(-s / (double)BATCH);
}

// ---------------------------------------------------------------------------
// Launch
// ---------------------------------------------------------------------------
extern "C" void kernel_launch(void* const* d_in, const int* in_sizes, int n_in,
                              void* d_out, int out_size)
{
    const int*   x     = (const int*)d_in[0];
    const int*   y     = (const int*)d_in[1];
    const float* emb   = (const float*)d_in[2];
    const float* Wq    = (const float*)d_in[3];
    const float* Wkv   = (const float*)d_in[4];
    const float* Wo    = (const float*)d_in[5];
    const float* Wf    = (const float*)d_in[6];
    const float* bf    = (const float*)d_in[7];
    float* out = (float*)d_out;

    __half *p_qb, *p_kb, *p_vb;
    unsigned char *p_h8, *p_att8, *p_w8qkv, *p_w8o;
    cudaGetSymbolAddress((void**)&p_qb,    g_qb);
    cudaGetSymbolAddress((void**)&p_kb,    g_kb);
    cudaGetSymbolAddress((void**)&p_vb,    g_vb);
    cudaGetSymbolAddress((void**)&p_h8,    g_h8);
    cudaGetSymbolAddress((void**)&p_att8,  g_att8);
    cudaGetSymbolAddress((void**)&p_w8qkv, g_w8qkv);
    cudaGetSymbolAddress((void**)&p_w8o,   g_w8o);

    cudaFuncSetAttribute((void*)gemm_fp8_kernel<false>,
                         cudaFuncAttributeMaxDynamicSharedMemorySize, GEMM_SMEM);
    cudaFuncSetAttribute((void*)gemm_fp8_kernel<true>,
                         cudaFuncAttributeMaxDynamicSharedMemorySize, GEMM_SMEM);
    cudaFuncSetAttribute(attn_kernel,
                         cudaFuncAttributeMaxDynamicSharedMemorySize, ATT_SMEM);

    // 1) merged prologue: fp8 transposes + logits zero + Wf f16 + fp8 gather
    prep_kernel<<<PREP_BLOCKS, 256>>>(x, emb, Wq, Wkv, Wo, Wf);

    // 2) fused QKV projection: fp8 GEMM, N = 3072, f16 outputs
    {
        int nx = 3 * EDIM / NT;              // 24
        gemm_fp8_kernel<false><<<dim3(nx * (ROWS / MT), 1), 256, GEMM_SMEM>>>(
            p_h8, p_w8qkv, nullptr, p_qb, p_kb, p_vb, nx);
    }

    // 3) attention (f16 tensor cores; writes fp8 att)
    attn_kernel<<<LSEQ * NHEAD / ATT_WARPS, 256, ATT_SMEM>>>();

    // 4) out = h + att @ Wo fused with logits (fp8 GEMM, fp8 residual)
    {
        int nx = EDIM / NT;                  // 8
        gemm_fp8_kernel<true><<<dim3(nx * (ROWS / MT), 1), 256, GEMM_SMEM>>>(
            p_att8, p_w8o, p_h8, nullptr, nullptr, nullptr, nx);
    }

    // 5) loss
    loss_kernel<<<1, 32>>>(y, bf, out);
}

// round 16
// speedup vs baseline: 1.0647x; 1.0647x over previous
#include <cuda_runtime.h>
#include <cuda_fp16.h>
#include <math.h>
#include <float.h>
#include <stdint.h>

// Problem constants
#define BATCH 32
#define LSEQ  2048
#define EDIM  1024
#define NHEAD 16
#define DHEAD 64
#define HD    (NHEAD * DHEAD)     // 1024
#define ROWS  (BATCH * LSEQ)      // 65536
#define FLAT  (LSEQ * EDIM)       // 2097152
#define NCLS  2

#define FP8_SCALE 32.0f

#define SMEM_SWIZZLE_128B(byte_offset) \
    ((byte_offset) ^ (((byte_offset) >> 3) & 0x70))

__device__ __forceinline__ uint32_t smem_to_u32(const void* smem_ptr) {
    uint32_t addr;
    asm("{ .reg .u64 tmp; cvta.to.shared.u64 tmp, %1; cvt.u32.u64 %0, tmp; }"
        : "=r"(addr) : "l"(smem_ptr));
    return addr;
}

__device__ __forceinline__ void cp_async16(uint32_t smem_addr, const void* gptr) {
    asm volatile("cp.async.cg.shared.global [%0], [%1], 16;"
                 :: "r"(smem_addr), "l"(gptr) : "memory");
}
__device__ __forceinline__ void cp_commit() {
    asm volatile("cp.async.commit_group;" ::: "memory");
}

__device__ __forceinline__ void ldmx4(uint32_t* r, uint32_t addr) {
    asm volatile("ldmatrix.sync.aligned.m8n8.x4.shared.b16 {%0,%1,%2,%3}, [%4];"
                 : "=r"(r[0]), "=r"(r[1]), "=r"(r[2]), "=r"(r[3]) : "r"(addr));
}
__device__ __forceinline__ void ldmx4t(uint32_t* r, uint32_t addr) {
    asm volatile("ldmatrix.sync.aligned.m8n8.x4.trans.shared.b16 {%0,%1,%2,%3}, [%4];"
                 : "=r"(r[0]), "=r"(r[1]), "=r"(r[2]), "=r"(r[3]) : "r"(addr));
}

// f16 inputs, f16 accumulator (GEMM mainloop — proven fastest path)
__device__ __forceinline__ void mma16816h(uint32_t* c, const uint32_t* a, const uint32_t* b) {
    asm volatile(
        "mma.sync.aligned.m16n8k16.row.col.f16.f16.f16.f16 "
        "{%0,%1}, {%2,%3,%4,%5}, {%6,%7}, {%0,%1};"
        : "+r"(c[0]), "+r"(c[1])
        : "r"(a[0]), "r"(a[1]), "r"(a[2]), "r"(a[3]), "r"(b[0]), "r"(b[1]));
}

// f16 inputs, f32 accumulator (attention)
__device__ __forceinline__ void mma16816f(float* c, const uint32_t* a, const uint32_t* b) {
    asm volatile(
        "mma.sync.aligned.m16n8k16.row.col.f32.f16.f16.f32 "
        "{%0,%1,%2,%3}, {%4,%5,%6,%7}, {%8,%9}, {%0,%1,%2,%3};"
        : "+f"(c[0]), "+f"(c[1]), "+f"(c[2]), "+f"(c[3])
        : "r"(a[0]), "r"(a[1]), "r"(a[2]), "r"(a[3]), "r"(b[0]), "r"(b[1]));
}

// fp8 helpers
__device__ __forceinline__ uint16_t pack_fp8x2(float lo, float hi) {
    uint16_t r;
    asm("cvt.rn.satfinite.e4m3x2.f32 %0, %1, %2;" : "=h"(r) : "f"(hi), "f"(lo));
    return r;
}
__device__ __forceinline__ uint32_t fp8x2_to_h2(uint16_t v) {
    uint32_t h2;
    asm("cvt.rn.f16x2.e4m3x2 %0, %1;" : "=r"(h2) : "h"(v));
    return h2;
}

// ---------------------------------------------------------------------------
// Device-global scratch
// ---------------------------------------------------------------------------
__device__ __half g_hb[(size_t)ROWS * EDIM];          // 128 MB f16 h
__device__ unsigned char g_q8[(size_t)ROWS * HD];     // 64 MB fp8(q*32)
__device__ unsigned char g_k8[(size_t)ROWS * HD];
__device__ unsigned char g_v8[(size_t)ROWS * HD];
__device__ __half g_att[(size_t)ROWS * HD];           // 128 MB f16 att
__device__ __half g_wqkv[(size_t)3 * HD * EDIM];      // f16 W^T
__device__ __half g_wo[(size_t)EDIM * HD];
__device__ __half g_wf16[(size_t)FLAT * NCLS];        // 8 MB f16 Wf
__device__ double g_logits[BATCH * NCLS];

// ---------------------------------------------------------------------------
// 1) MERGED prologue (R14): transposes -> f16 (+logits zero), Wf -> f16,
//    gather -> f16.
// ---------------------------------------------------------------------------
#define TRANS_BLOCKS 4096
#define WF_BLOCKS    2048
#define PREP_BLOCKS  (TRANS_BLOCKS + WF_BLOCKS + ROWS)

__global__ __launch_bounds__(256) void prep_kernel(
    const int* __restrict__ x, const float* __restrict__ emb,
    const float* __restrict__ Wq, const float* __restrict__ Wkv,
    const float* __restrict__ Wo, const float* __restrict__ Wf)
{
    __shared__ float tile[32][33];
    int bid = blockIdx.x;

    if (bid < TRANS_BLOCKS) {
        int z  = bid >> 10;
        int zi = bid & 1023;
        int bx = (zi & 31) * 32;
        int by = (zi >> 5) * 32;

        if (bid == 0 && threadIdx.x < BATCH * NCLS)
            g_logits[threadIdx.x] = 0.0;

        const float* in; int ldin, coloff; __half* out;
        switch (z) {
            case 0: in = Wq;  ldin = HD;     coloff = 0;  out = g_wqkv;                         break;
            case 1: in = Wkv; ldin = 2 * HD; coloff = 0;  out = g_wqkv + (size_t)HD * EDIM;     break;
            case 2: in = Wkv; ldin = 2 * HD; coloff = HD; out = g_wqkv + (size_t)2 * HD * EDIM; break;
            default: in = Wo; ldin = EDIM;   coloff = 0;  out = g_wo;                           break;
        }
        int tx = threadIdx.x & 31;
        int ty = threadIdx.x >> 5;
        for (int i = ty; i < 32; i += 8)
            tile[i][tx] = in[(size_t)(by + i) * ldin + coloff + bx + tx];
        __syncthreads();
        for (int i = ty; i < 32; i += 8)
            out[(size_t)(bx + i) * 1024 + by + tx] = __float2half(tile[tx][i]);
    } else if (bid < TRANS_BLOCKS + WF_BLOCKS) {
        size_t base = (size_t)(bid - TRANS_BLOCKS) * 2048 + (size_t)threadIdx.x * 8;
        float4 f0 = *(const float4*)(Wf + base);
        float4 f1 = *(const float4*)(Wf + base + 4);
        __half2 h0 = __floats2half2_rn(f0.x, f0.y);
        __half2 h1 = __floats2half2_rn(f0.z, f0.w);
        __half2 h2 = __floats2half2_rn(f1.x, f1.y);
        __half2 h3 = __floats2half2_rn(f1.z, f1.w);
        uint4 o;
        o.x = *(uint32_t*)&h0; o.y = *(uint32_t*)&h1;
        o.z = *(uint32_t*)&h2; o.w = *(uint32_t*)&h3;
        *(uint4*)(g_wf16 + base) = o;
    } else {
        int row = bid - TRANS_BLOCKS - WF_BLOCKS;
        int v = x[row];
        int t = threadIdx.x;
        float4 f = ((const float4*)(emb + (size_t)v * EDIM))[t];
        __half2 lo = __floats2half2_rn(f.x, f.y);
        __half2 hi = __floats2half2_rn(f.z, f.w);
        uint2 p;
        p.x = *(uint32_t*)&lo;
        p.y = *(uint32_t*)&hi;
        ((uint2*)(g_hb + (size_t)row * EDIM))[t] = p;
    }
}

// ---------------------------------------------------------------------------
// 2) f16 GEMM (R14 mainloop frozen). !LOGITS epilogue now packs fp8 (x32)
//    into q8/k8/v8. LOGITS epilogue identical to R14 (f16 Wf dot + atomics).
// ---------------------------------------------------------------------------
#define MT 128
#define NT 128
#define A_BYTES (MT * 128)
#define B_BYTES (NT * 128)
#define NCHUNKS 16
#define STAGES 3
#define GEMM_SMEM (STAGES * (A_BYTES + B_BYTES) + 1024)   // 99328

__device__ __forceinline__ void load_chunk(
    uint32_t abuf, uint32_t bbuf,
    const char* Abase, const char* Bbase, int c, int t)
{
#pragma unroll
    for (int i = 0; i < 4; i++) {
        int seg = t + 256 * i;
        int r = seg >> 3, s = seg & 7;
        uint32_t off = SMEM_SWIZZLE_128B((uint32_t)(r * 128 + s * 16));
        cp_async16(abuf + off, Abase + (size_t)r * 2048 + c * 128 + s * 16);
    }
#pragma unroll
    for (int i = 0; i < 4; i++) {
        int seg = t + 256 * i;
        int r = seg >> 3, s = seg & 7;
        uint32_t off = SMEM_SWIZZLE_128B((uint32_t)(r * 128 + s * 16));
        cp_async16(bbuf + off, Bbase + (size_t)r * 2048 + c * 128 + s * 16);
    }
}

template<bool LOGITS>
__global__ __launch_bounds__(256, 2) void gemm_f16_kernel(
    const __half* __restrict__ A,
    const __half* __restrict__ Bt,
    const __half* __restrict__ Res,
    unsigned char* __restrict__ D0,
    unsigned char* __restrict__ D1,
    unsigned char* __restrict__ D2,
    int nxblocks)
{
    extern __shared__ char smem[];
    uint32_t base = (smem_to_u32(smem) + 1023) & ~1023u;
    uint32_t a_sm[STAGES], b_sm[STAGES];
#pragma unroll
    for (int s = 0; s < STAGES; s++) {
        a_sm[s] = base + s * (A_BYTES + B_BYTES);
        b_sm[s] = a_sm[s] + A_BYTES;
    }

    int t = threadIdx.x;
    int wid = t >> 5, lane = t & 31;
    int mwarp0 = (wid & 3) * 32;
    int nwarp0 = (wid >> 2) * 64;

    int bid = blockIdx.x;
    int bx, by;
    if (LOGITS) {
        int b    = bid & 31;
        bx       = (bid >> 5) & 7;
        int lblk = bid >> 8;
        by = b * 16 + lblk;
    } else {
        int group = bid / (nxblocks * 8);
        int rem   = bid % (nxblocks * 8);
        bx = rem % nxblocks;
        by = group * 8 + (rem / nxblocks);
    }

    size_t row0 = (size_t)by * MT;
    int col0 = bx * NT;

    int tgt = col0 >> 10;
    int colc = col0 & 1023;
    unsigned char* D = (tgt == 0) ? D0 : ((tgt == 1) ? D1 : D2);

    const char* Abase = (const char*)(A + row0 * 1024);
    const char* Bbase = (const char*)(Bt + (size_t)col0 * 1024);

    int g = lane & 7, sel = lane >> 3;
    int mA = mwarp0 + g + (sel & 1) * 8;
    uint32_t aRow[2] = { (uint32_t)(mA * 128), (uint32_t)((mA + 16) * 128) };
    uint32_t aKb = (uint32_t)((sel >> 1) * 16);
    uint32_t aX  = (uint32_t)((mA & 7) << 4);

    int nB = nwarp0 + g + ((sel >> 1) * 8);
    uint32_t bRow[4] = { (uint32_t)(nB * 128), (uint32_t)((nB + 16) * 128),
                         (uint32_t)((nB + 32) * 128), (uint32_t)((nB + 48) * 128) };
    uint32_t bKb = (uint32_t)((sel & 1) * 16);
    uint32_t bX  = (uint32_t)((nB & 7) << 4);

    uint32_t hacc[2][8][2];
#pragma unroll
    for (int i = 0; i < 2; i++)
#pragma unroll
        for (int j = 0; j < 8; j++) { hacc[i][j][0] = 0u; hacc[i][j][1] = 0u; }

    load_chunk(a_sm[0], b_sm[0], Abase, Bbase, 0, t); cp_commit();
    load_chunk(a_sm[1], b_sm[1], Abase, Bbase, 1, t); cp_commit();

#pragma unroll
    for (int c = 0; c < NCHUNKS; c++) {
        int stage = c % STAGES;
        if (c < NCHUNKS - 1) {
            asm volatile("cp.async.wait_group 1;" ::: "memory");
        } else {
            asm volatile("cp.async.wait_group 0;" ::: "memory");
        }
        __syncthreads();
        if (c + 2 < NCHUNKS) {
            int ns = (c + 2) % STAGES;
            load_chunk(a_sm[ns], b_sm[ns], Abase, Bbase, c + 2, t);
            cp_commit();
        }

        uint32_t ab = a_sm[stage], bb = b_sm[stage];
#pragma unroll
        for (int s = 0; s < 4; s++) {
            uint32_t kb0 = (uint32_t)(s * 32);
            uint32_t afrag[2][4], bfrag[4][4];
#pragma unroll
            for (int mi = 0; mi < 2; mi++)
                ldmx4(afrag[mi], ab + aRow[mi] + ((aKb + kb0) ^ aX));
#pragma unroll
            for (int j = 0; j < 4; j++)
                ldmx4(bfrag[j], bb + bRow[j] + ((bKb + kb0) ^ bX));
#pragma unroll
            for (int mi = 0; mi < 2; mi++)
#pragma unroll
                for (int j = 0; j < 4; j++) {
                    mma16816h(hacc[mi][2 * j],     afrag[mi], &bfrag[j][0]);
                    mma16816h(hacc[mi][2 * j + 1], afrag[mi], &bfrag[j][2]);
                }
        }
    }

    if (!LOGITS) {
        // q/k/v epilogue: pack fp8 (x32)
#pragma unroll
        for (int mi = 0; mi < 2; mi++) {
            size_t r0 = row0 + mwarp0 + mi * 16 + (lane >> 2);
#pragma unroll
            for (int nj = 0; nj < 8; nj++) {
                int col = colc + nwarp0 + nj * 8 + (lane & 3) * 2;
                float2 f0 = __half22float2(*(__half2*)&hacc[mi][nj][0]);
                float2 f1 = __half22float2(*(__half2*)&hacc[mi][nj][1]);
                uint16_t p0 = pack_fp8x2(f0.x * FP8_SCALE, f0.y * FP8_SCALE);
                uint16_t p1 = pack_fp8x2(f1.x * FP8_SCALE, f1.y * FP8_SCALE);
                *(uint16_t*)(D + r0 * 1024 + col)       = p0;
                *(uint16_t*)(D + (r0 + 8) * 1024 + col) = p1;
            }
        }
    } else {
        // Fused-logits epilogue (R14): out = acc + res; dot with f16 Wf.
        float a0 = 0.f, a1 = 0.f;
        int bidx = (int)(row0 >> 11);
#pragma unroll
        for (int mi = 0; mi < 2; mi++) {
            size_t r0 = row0 + mwarp0 + mi * 16 + (lane >> 2);
            int l0 = (int)(r0 & 2047);
#pragma unroll
            for (int nj = 0; nj < 8; nj++) {
                int col = colc + nwarp0 + nj * 8 + (lane & 3) * 2;
                uint32_t v0 = hacc[mi][nj][0];
                uint32_t v1 = hacc[mi][nj][1];
                uint32_t u0 = *(const uint32_t*)(Res + r0 * 1024 + col);
                uint32_t u1 = *(const uint32_t*)(Res + (r0 + 8) * 1024 + col);
                __half2 s0 = __hadd2(*(__half2*)&v0, *(__half2*)&u0);
                __half2 s1 = __hadd2(*(__half2*)&v1, *(__half2*)&u1);
                float2 f0 = __half22float2(s0);
                float2 f1 = __half22float2(s1);
                uint2 w0u = *(const uint2*)(g_wf16 + ((size_t)l0 * 1024 + col) * 2);
                uint2 w1u = *(const uint2*)(g_wf16 + ((size_t)(l0 + 8) * 1024 + col) * 2);
                float2 w00 = __half22float2(*(__half2*)&w0u.x);
                float2 w01 = __half22float2(*(__half2*)&w0u.y);
                float2 w10 = __half22float2(*(__half2*)&w1u.x);
                float2 w11 = __half22float2(*(__half2*)&w1u.y);
                a0 += f0.x * w00.x + f0.y * w01.x + f1.x * w10.x + f1.y * w11.x;
                a1 += f0.x * w00.y + f0.y * w01.y + f1.x * w10.y + f1.y * w11.y;
            }
        }
#pragma unroll
        for (int off = 16; off >= 1; off >>= 1) {
            a0 += __shfl_xor_sync(0xffffffffu, a0, off);
            a1 += __shfl_xor_sync(0xffffffffu, a1, off);
        }
        if (lane == 0) {
            atomicAdd(&g_logits[2 * bidx],     (double)a0);
            atomicAdd(&g_logits[2 * bidx + 1], (double)a1);
        }
    }
}

// ---------------------------------------------------------------------------
// 3) Attention: fp8 q/k/v loads (1/4 bytes), in-smem convert to f16 (/32),
//    then the proven f16 tensor-core path. Writes f16 att to g_att.
// ---------------------------------------------------------------------------
#define ATT_WARPS 8
#define ATT_SMEM (ATT_WARPS * 3 * 4096)   // 96 KB (2 CTA/SM preserved)
#define ROWSTRIDE_E (LSEQ * NHEAD * DHEAD)   // per-batch stride (elems = bytes for fp8)

__global__ __launch_bounds__(256) void attn_kernel()
{
    extern __shared__ char asmem[];
    int t = threadIdx.x, w = t >> 5, lane = t & 31;
    char* wmem = asmem + w * 12288;
    uint32_t wbase = smem_to_u32(asmem) + w * 12288;
    uint32_t qsm = wbase, ksm = wbase + 4096, vsm = wbase + 8192;

    int pair = blockIdx.x * ATT_WARPS + w;
    int l = pair >> 4, n = pair & 15;
    size_t ebase = ((size_t)l * NHEAD + n) * DHEAD;
    const char* qg = (const char*)(g_q8 + ebase);
    const char* kg = (const char*)(g_k8 + ebase);
    const char* vg = (const char*)(g_v8 + ebase);

    // ---- load fp8 tiles [32 x 64 B] into the BACK half of each 4KB region
#pragma unroll
    for (int i = 0; i < 4; i++) {
        int s = lane + 32 * i;                 // 0..127
        int row = s >> 2, sub = s & 3;
        size_t go = (size_t)row * ROWSTRIDE_E + sub * 16;
        uint32_t so = 2048u + (uint32_t)(row * 64 + sub * 16);
        cp_async16(qsm + so, qg + go);
        cp_async16(ksm + so, kg + go);
        cp_async16(vsm + so, vg + go);
    }
    cp_commit();
    asm volatile("cp.async.wait_group 0;" ::: "memory");
    __syncwarp();

    // ---- convert fp8 -> f16 (/32) into the standard swizzled layout ----
    const __half2 inv32 = __float2half2_rn(0.03125f);
    uint32_t xorv = (uint32_t)((lane & 7) << 4);
#pragma unroll
    for (int ti = 0; ti < 3; ti++) {
        char* tb = wmem + ti * 4096;
        uint4 in[4];
#pragma unroll
        for (int k = 0; k < 4; k++)
            in[k] = *(uint4*)(tb + 2048 + lane * 64 + k * 16);
        __syncwarp();
#pragma unroll
        for (int k = 0; k < 4; k++) {
            uint32_t ws[4] = { in[k].x, in[k].y, in[k].z, in[k].w };
            uint32_t r[8];
#pragma unroll
            for (int i = 0; i < 4; i++) {
                uint32_t lo = fp8x2_to_h2((uint16_t)(ws[i] & 0xffff));
                uint32_t hi = fp8x2_to_h2((uint16_t)(ws[i] >> 16));
                __half2 l2 = __hmul2(*(__half2*)&lo, inv32);
                __half2 h2 = __hmul2(*(__half2*)&hi, inv32);
                r[2 * i]     = *(uint32_t*)&l2;
                r[2 * i + 1] = *(uint32_t*)&h2;
            }
            uint32_t b0 = (uint32_t)(lane * 128) + (((uint32_t)(k * 32))      ^ xorv);
            uint32_t b1 = (uint32_t)(lane * 128) + (((uint32_t)(k * 32 + 16)) ^ xorv);
            *(uint4*)(tb + b0) = make_uint4(r[0], r[1], r[2], r[3]);
            *(uint4*)(tb + b1) = make_uint4(r[4], r[5], r[6], r[7]);
        }
        __syncwarp();
    }

    int g8 = lane & 7, sel = lane >> 3;

    // ---- S = Q K^T ----
    float c[2][4][4];
#pragma unroll
    for (int mi = 0; mi < 2; mi++)
#pragma unroll
        for (int j = 0; j < 4; j++)
#pragma unroll
            for (int k = 0; k < 4; k++) c[mi][j][k] = 0.f;

#pragma unroll
    for (int kc = 0; kc < 4; kc++) {
        uint32_t kb = kc * 32;
        uint32_t af[2][4], bfr[2][4];
#pragma unroll
        for (int mi = 0; mi < 2; mi++) {
            int row = mi * 16 + g8 + (sel & 1) * 8;
            uint32_t off = row * 128 + ((kb + (sel >> 1) * 16) ^ ((row & 7) << 4));
            ldmx4(af[mi], qsm + off);
        }
#pragma unroll
        for (int nj2 = 0; nj2 < 2; nj2++) {
            int row = nj2 * 16 + g8 + (sel >> 1) * 8;
            uint32_t off = row * 128 + ((kb + (sel & 1) * 16) ^ ((row & 7) << 4));
            ldmx4(bfr[nj2], ksm + off);
        }
#pragma unroll
        for (int mi = 0; mi < 2; mi++)
#pragma unroll
            for (int nj2 = 0; nj2 < 2; nj2++) {
                mma16816f(c[mi][2 * nj2],     af[mi], &bfr[nj2][0]);
                mma16816f(c[mi][2 * nj2 + 1], af[mi], &bfr[nj2][2]);
            }
    }

    // ---- softmax ----
    float inv0[2], inv1[2];
#pragma unroll
    for (int mi = 0; mi < 2; mi++) {
        float m0 = -FLT_MAX, m1 = -FLT_MAX;
#pragma unroll
        for (int j = 0; j < 4; j++) {
#pragma unroll
            for (int k = 0; k < 4; k++) c[mi][j][k] *= 0.125f;
            m0 = fmaxf(m0, fmaxf(c[mi][j][0], c[mi][j][1]));
            m1 = fmaxf(m1, fmaxf(c[mi][j][2], c[mi][j][3]));
        }
        m0 = fmaxf(m0, __shfl_xor_sync(0xffffffffu, m0, 1));
        m0 = fmaxf(m0, __shfl_xor_sync(0xffffffffu, m0, 2));
        m1 = fmaxf(m1, __shfl_xor_sync(0xffffffffu, m1, 1));
        m1 = fmaxf(m1, __shfl_xor_sync(0xffffffffu, m1, 2));
        float s0 = 0.f, s1 = 0.f;
#pragma unroll
        for (int j = 0; j < 4; j++) {
            c[mi][j][0] = __expf(c[mi][j][0] - m0);
            c[mi][j][1] = __expf(c[mi][j][1] - m0);
            c[mi][j][2] = __expf(c[mi][j][2] - m1);
            c[mi][j][3] = __expf(c[mi][j][3] - m1);
            s0 += c[mi][j][0] + c[mi][j][1];
            s1 += c[mi][j][2] + c[mi][j][3];
        }
        s0 += __shfl_xor_sync(0xffffffffu, s0, 1);
        s0 += __shfl_xor_sync(0xffffffffu, s0, 2);
        s1 += __shfl_xor_sync(0xffffffffu, s1, 1);
        s1 += __shfl_xor_sync(0xffffffffu, s1, 2);
        inv0[mi] = 1.f / s0;
        inv1[mi] = 1.f / s1;
    }

    // ---- pack P ----
    uint32_t pf[2][2][4];
#pragma unroll
    for (int mi = 0; mi < 2; mi++)
#pragma unroll
        for (int kc = 0; kc < 2; kc++) {
            __half2 x0 = __floats2half2_rn(c[mi][2 * kc][0],     c[mi][2 * kc][1]);
            __half2 x1 = __floats2half2_rn(c[mi][2 * kc][2],     c[mi][2 * kc][3]);
            __half2 x2 = __floats2half2_rn(c[mi][2 * kc + 1][0], c[mi][2 * kc + 1][1]);
            __half2 x3 = __floats2half2_rn(c[mi][2 * kc + 1][2], c[mi][2 * kc + 1][3]);
            pf[mi][kc][0] = *(uint32_t*)&x0;
            pf[mi][kc][1] = *(uint32_t*)&x1;
            pf[mi][kc][2] = *(uint32_t*)&x2;
            pf[mi][kc][3] = *(uint32_t*)&x3;
        }

    // ---- att = P V ----
    float cv[2][8][4];
#pragma unroll
    for (int mi = 0; mi < 2; mi++)
#pragma unroll
        for (int j = 0; j < 8; j++)
#pragma unroll
            for (int k = 0; k < 4; k++) cv[mi][j][k] = 0.f;

#pragma unroll
    for (int kc = 0; kc < 2; kc++) {
#pragma unroll
        for (int dj2 = 0; dj2 < 4; dj2++) {
            int row = kc * 16 + g8 + (sel & 1) * 8;
            uint32_t colb = dj2 * 32 + (sel >> 1) * 16;
            uint32_t off = row * 128 + (colb ^ ((row & 7) << 4));
            uint32_t bv[4];
            ldmx4t(bv, vsm + off);
#pragma unroll
            for (int mi = 0; mi < 2; mi++) {
                mma16816f(cv[mi][2 * dj2],     pf[mi][kc], &bv[0]);
                mma16816f(cv[mi][2 * dj2 + 1], pf[mi][kc], &bv[2]);
            }
        }
    }

    // ---- normalize + store f16 att ----
    int r = lane >> 2, cq = (lane & 3) * 2;
#pragma unroll
    for (int mi = 0; mi < 2; mi++) {
        int i0 = mi * 16 + r;
        __half* o0 = g_att + ebase + (size_t)i0 * ROWSTRIDE_E;
        __half* o1 = o0 + (size_t)8 * ROWSTRIDE_E;
#pragma unroll
        for (int dj = 0; dj < 8; dj++) {
            int col = dj * 8 + cq;
            __half2 h0 = __floats2half2_rn(cv[mi][dj][0] * inv0[mi],
                                           cv[mi][dj][1] * inv0[mi]);
            __half2 h1 = __floats2half2_rn(cv[mi][dj][2] * inv1[mi],
                                           cv[mi][dj][3] * inv1[mi]);
            *(uint32_t*)(o0 + col) = *(uint32_t*)&h0;
            *(uint32_t*)(o1 + col) = *(uint32_t*)&h1;
        }
    }
}

// ---------------------------------------------------------------------------
// 4) Loss
// ---------------------------------------------------------------------------
__global__ void loss_kernel(const int* __restrict__ y,
                            const float* __restrict__ bf,
                            float* __restrict__ out)
{
    if (threadIdx.x != 0 || blockIdx.x != 0) return;
    double s = 0.0;
    double b0 = (double)bf[0], b1 = (double)bf[1];
    for (int b = 0; b < BATCH; b++) {
        double l0 = g_logits[2 * b]     + b0;
        double l1 = g_logits[2 * b + 1] + b1;
        double m  = l0 > l1 ? l0 : l1;
        double lse = m + log(exp(l0 - m) + exp(l1 - m));
        double lp  = (y[b] == 0 ? l0 : l1) - lse;
        s += lp;
    }
    out[0] = (float)(-s / (double)BATCH);
}

// ---------------------------------------------------------------------------
// Launch
// ---------------------------------------------------------------------------
extern "C" void kernel_launch(void* const* d_in, const int* in_sizes, int n_in,
                              void* d_out, int out_size)
{
    const int*   x     = (const int*)d_in[0];
    const int*   y     = (const int*)d_in[1];
    const float* emb   = (const float*)d_in[2];
    const float* Wq    = (const float*)d_in[3];
    const float* Wkv   = (const float*)d_in[4];
    const float* Wo    = (const float*)d_in[5];
    const float* Wf    = (const float*)d_in[6];
    const float* bf    = (const float*)d_in[7];
    float* out = (float*)d_out;

    __half *p_hb, *p_att, *p_wqkv, *p_wo;
    unsigned char *p_q8, *p_k8, *p_v8;
    cudaGetSymbolAddress((void**)&p_hb,   g_hb);
    cudaGetSymbolAddress((void**)&p_att,  g_att);
    cudaGetSymbolAddress((void**)&p_wqkv, g_wqkv);
    cudaGetSymbolAddress((void**)&p_wo,   g_wo);
    cudaGetSymbolAddress((void**)&p_q8,   g_q8);
    cudaGetSymbolAddress((void**)&p_k8,   g_k8);
    cudaGetSymbolAddress((void**)&p_v8,   g_v8);

    cudaFuncSetAttribute((void*)gemm_f16_kernel<false>,
                         cudaFuncAttributeMaxDynamicSharedMemorySize, GEMM_SMEM);
    cudaFuncSetAttribute((void*)gemm_f16_kernel<true>,
                         cudaFuncAttributeMaxDynamicSharedMemorySize, GEMM_SMEM);
    cudaFuncSetAttribute(attn_kernel,
                         cudaFuncAttributeMaxDynamicSharedMemorySize, ATT_SMEM);

    // 1) merged prologue
    prep_kernel<<<PREP_BLOCKS, 256>>>(x, emb, Wq, Wkv, Wo, Wf);

    // 2) fused QKV projection (f16 GEMM, fp8 q/k/v outputs)
    {
        int nx = 3 * EDIM / NT;              // 24
        gemm_f16_kernel<false><<<dim3(nx * (ROWS / MT), 1), 256, GEMM_SMEM>>>(
            p_hb, p_wqkv, nullptr, p_q8, p_k8, p_v8, nx);
    }

    // 3) attention (fp8 in, f16 compute, f16 att out)
    attn_kernel<<<LSEQ * NHEAD / ATT_WARPS, 256, ATT_SMEM>>>();

    // 4) out = h + att @ Wo fused with logits (f16 GEMM)
    {
        int nx = EDIM / NT;                  // 8
        gemm_f16_kernel<true><<<dim3(nx * (ROWS / MT), 1), 256, GEMM_SMEM>>>(
            p_att, p_wo, p_hb, nullptr, nullptr, nullptr, nx);
    }

    // 5) loss
    loss_kernel<<<1, 32>>>(y, bf, out);
}

// round 17
// speedup vs baseline: 1.1090x; 1.0416x over previous
#include <cuda_runtime.h>
#include <cuda_fp16.h>
#include <math.h>
#include <float.h>
#include <stdint.h>

// Problem constants
#define BATCH 32
#define LSEQ  2048
#define EDIM  1024
#define NHEAD 16
#define DHEAD 64
#define HD    (NHEAD * DHEAD)     // 1024
#define ROWS  (BATCH * LSEQ)      // 65536
#define FLAT  (LSEQ * EDIM)       // 2097152
#define NCLS  2

#define SMEM_SWIZZLE_128B(byte_offset) \
    ((byte_offset) ^ (((byte_offset) >> 3) & 0x70))

__device__ __forceinline__ uint32_t smem_to_u32(const void* smem_ptr) {
    uint32_t addr;
    asm("{ .reg .u64 tmp; cvta.to.shared.u64 tmp, %1; cvt.u32.u64 %0, tmp; }"
        : "=r"(addr) : "l"(smem_ptr));
    return addr;
}

__device__ __forceinline__ void cp_async16(uint32_t smem_addr, const void* gptr) {
    asm volatile("cp.async.cg.shared.global [%0], [%1], 16;"
                 :: "r"(smem_addr), "l"(gptr) : "memory");
}
__device__ __forceinline__ void cp_commit() {
    asm volatile("cp.async.commit_group;" ::: "memory");
}

__device__ __forceinline__ void ldmx4(uint32_t* r, uint32_t addr) {
    asm volatile("ldmatrix.sync.aligned.m8n8.x4.shared.b16 {%0,%1,%2,%3}, [%4];"
                 : "=r"(r[0]), "=r"(r[1]), "=r"(r[2]), "=r"(r[3]) : "r"(addr));
}
__device__ __forceinline__ void ldmx4t(uint32_t* r, uint32_t addr) {
    asm volatile("ldmatrix.sync.aligned.m8n8.x4.trans.shared.b16 {%0,%1,%2,%3}, [%4];"
                 : "=r"(r[0]), "=r"(r[1]), "=r"(r[2]), "=r"(r[3]) : "r"(addr));
}

// f16 inputs, f16 accumulator
__device__ __forceinline__ void mma16816h(uint32_t* c, const uint32_t* a, const uint32_t* b) {
    asm volatile(
        "mma.sync.aligned.m16n8k16.row.col.f16.f16.f16.f16 "
        "{%0,%1}, {%2,%3,%4,%5}, {%6,%7}, {%0,%1};"
        : "+r"(c[0]), "+r"(c[1])
        : "r"(a[0]), "r"(a[1]), "r"(a[2]), "r"(a[3]), "r"(b[0]), "r"(b[1]));
}

// f16 inputs, f32 accumulator (attention)
__device__ __forceinline__ void mma16816f(float* c, const uint32_t* a, const uint32_t* b) {
    asm volatile(
        "mma.sync.aligned.m16n8k16.row.col.f32.f16.f16.f32 "
        "{%0,%1,%2,%3}, {%4,%5,%6,%7}, {%8,%9}, {%0,%1,%2,%3};"
        : "+f"(c[0]), "+f"(c[1]), "+f"(c[2]), "+f"(c[3])
        : "r"(a[0]), "r"(a[1]), "r"(a[2]), "r"(a[3]), "r"(b[0]), "r"(b[1]));
}

// ---------------------------------------------------------------------------
// Device-global scratch (f16)
// ---------------------------------------------------------------------------
__device__ __half g_hb[(size_t)ROWS * EDIM];     // 128 MB
__device__ __half g_qb[(size_t)ROWS * HD];       // q, then att (in place)
__device__ __half g_kb[(size_t)ROWS * HD];
__device__ __half g_vb[(size_t)ROWS * HD];
__device__ __half g_wqkv[(size_t)3 * HD * EDIM]; // fused Wq^T|Wk^T|Wv^T
__device__ __half g_wo[(size_t)EDIM * HD];
__device__ __half g_wf16[(size_t)FLAT * NCLS];   // 8 MB (f16 copy of Wf)
__device__ double g_logits[BATCH * NCLS];

// ---------------------------------------------------------------------------
// 1) MERGED prologue: weight transposes (+logits zero), Wf f32->f16 convert,
//    AND embedding gather, in one launch.
// ---------------------------------------------------------------------------
#define TRANS_BLOCKS 4096          // 32 x 32 x 4
#define WF_BLOCKS    2048
#define PREP_BLOCKS  (TRANS_BLOCKS + WF_BLOCKS + ROWS)

__global__ __launch_bounds__(256) void prep_kernel(
    const int* __restrict__ x, const float* __restrict__ emb,
    const float* __restrict__ Wq, const float* __restrict__ Wkv,
    const float* __restrict__ Wo, const float* __restrict__ Wf,
    __half* __restrict__ wqkv, __half* __restrict__ wo)
{
    __shared__ float tile[32][33];
    int bid = blockIdx.x;

    if (bid < TRANS_BLOCKS) {
        // ---- weight transpose + convert ----
        int z  = bid >> 10;
        int zi = bid & 1023;
        int bx = (zi & 31) * 32;     // n block
        int by = (zi >> 5) * 32;     // k block

        if (bid == 0 && threadIdx.x < BATCH * NCLS)
            g_logits[threadIdx.x] = 0.0;

        const float* in; int ldin, coloff; __half* out;
        switch (z) {
            case 0: in = Wq;  ldin = HD;     coloff = 0;  out = wqkv;                         break;
            case 1: in = Wkv; ldin = 2 * HD; coloff = 0;  out = wqkv + (size_t)HD * EDIM;     break;
            case 2: in = Wkv; ldin = 2 * HD; coloff = HD; out = wqkv + (size_t)2 * HD * EDIM; break;
            default: in = Wo; ldin = EDIM;   coloff = 0;  out = wo;                           break;
        }
        int tx = threadIdx.x & 31;
        int ty = threadIdx.x >> 5;
        for (int i = ty; i < 32; i += 8)
            tile[i][tx] = in[(size_t)(by + i) * ldin + coloff + bx + tx];
        __syncthreads();
        for (int i = ty; i < 32; i += 8)
            out[(size_t)(bx + i) * 1024 + by + tx] = __float2half(tile[tx][i]);
    } else if (bid < TRANS_BLOCKS + WF_BLOCKS) {
        // ---- Wf f32 -> f16 ----
        size_t base = (size_t)(bid - TRANS_BLOCKS) * 2048 + (size_t)threadIdx.x * 8;
        float4 f0 = *(const float4*)(Wf + base);
        float4 f1 = *(const float4*)(Wf + base + 4);
        __half2 h0 = __floats2half2_rn(f0.x, f0.y);
        __half2 h1 = __floats2half2_rn(f0.z, f0.w);
        __half2 h2 = __floats2half2_rn(f1.x, f1.y);
        __half2 h3 = __floats2half2_rn(f1.z, f1.w);
        uint4 o;
        o.x = *(uint32_t*)&h0; o.y = *(uint32_t*)&h1;
        o.z = *(uint32_t*)&h2; o.w = *(uint32_t*)&h3;
        *(uint4*)(g_wf16 + base) = o;
    } else {
        // ---- embedding gather -> f16 ----
        int row = bid - TRANS_BLOCKS - WF_BLOCKS;
        int v = x[row];
        int t = threadIdx.x;
        float4 f = ((const float4*)(emb + (size_t)v * EDIM))[t];
        __half2 lo = __floats2half2_rn(f.x, f.y);
        __half2 hi = __floats2half2_rn(f.z, f.w);
        uint2 p;
        p.x = *(uint32_t*)&lo;
        p.y = *(uint32_t*)&hi;
        ((uint2*)(g_hb + (size_t)row * EDIM))[t] = p;
    }
}

// ---------------------------------------------------------------------------
// 2) f16 tensor-core GEMM (128x128, 256 thr, 3-stage, 2 CTA/SM). R14 exact.
// ---------------------------------------------------------------------------
#define MT 128
#define NT 128
#define A_BYTES (MT * 128)
#define B_BYTES (NT * 128)
#define NCHUNKS 16
#define STAGES 3
#define GEMM_SMEM (STAGES * (A_BYTES + B_BYTES) + 1024)   // 99328

__device__ __forceinline__ void load_chunk(
    uint32_t abuf, uint32_t bbuf,
    const char* Abase, const char* Bbase, int c, int t)
{
#pragma unroll
    for (int i = 0; i < 4; i++) {
        int seg = t + 256 * i;
        int r = seg >> 3, s = seg & 7;
        uint32_t off = SMEM_SWIZZLE_128B((uint32_t)(r * 128 + s * 16));
        cp_async16(abuf + off, Abase + (size_t)r * 2048 + c * 128 + s * 16);
    }
#pragma unroll
    for (int i = 0; i < 4; i++) {
        int seg = t + 256 * i;
        int r = seg >> 3, s = seg & 7;
        uint32_t off = SMEM_SWIZZLE_128B((uint32_t)(r * 128 + s * 16));
        cp_async16(bbuf + off, Bbase + (size_t)r * 2048 + c * 128 + s * 16);
    }
}

template<bool RES, bool LOGITS>
__global__ __launch_bounds__(256, 2) void gemm_f16_kernel(
    const __half* __restrict__ A,
    const __half* __restrict__ Bt,
    const __half* __restrict__ Res,
    __half* __restrict__ D0,
    __half* __restrict__ D1,
    __half* __restrict__ D2,
    int nxblocks)
{
    extern __shared__ char smem[];
    uint32_t base = (smem_to_u32(smem) + 1023) & ~1023u;
    uint32_t a_sm[STAGES], b_sm[STAGES];
#pragma unroll
    for (int s = 0; s < STAGES; s++) {
        a_sm[s] = base + s * (A_BYTES + B_BYTES);
        b_sm[s] = a_sm[s] + A_BYTES;
    }

    int t = threadIdx.x;
    int wid = t >> 5, lane = t & 31;
    int mwarp0 = (wid & 3) * 32;
    int nwarp0 = (wid >> 2) * 64;

    int bid = blockIdx.x;
    int bx, by;
    if (LOGITS) {
        int b    = bid & 31;
        bx       = (bid >> 5) & 7;
        int lblk = bid >> 8;
        by = b * 16 + lblk;
    } else {
        int group = bid / (nxblocks * 8);
        int rem   = bid % (nxblocks * 8);
        bx = rem % nxblocks;
        by = group * 8 + (rem / nxblocks);
    }

    size_t row0 = (size_t)by * MT;
    int col0 = bx * NT;

    int tgt = col0 >> 10;
    int colc = col0 & 1023;
    __half* D = (tgt == 0) ? D0 : ((tgt == 1) ? D1 : D2);

    const char* Abase = (const char*)(A + row0 * 1024);
    const char* Bbase = (const char*)(Bt + (size_t)col0 * 1024);

    int g = lane & 7, sel = lane >> 3;
    int mA = mwarp0 + g + (sel & 1) * 8;
    uint32_t aRow[2] = { (uint32_t)(mA * 128), (uint32_t)((mA + 16) * 128) };
    uint32_t aKb = (uint32_t)((sel >> 1) * 16);
    uint32_t aX  = (uint32_t)((mA & 7) << 4);

    int nB = nwarp0 + g + ((sel >> 1) * 8);
    uint32_t bRow[4] = { (uint32_t)(nB * 128), (uint32_t)((nB + 16) * 128),
                         (uint32_t)((nB + 32) * 128), (uint32_t)((nB + 48) * 128) };
    uint32_t bKb = (uint32_t)((sel & 1) * 16);
    uint32_t bX  = (uint32_t)((nB & 7) << 4);

    uint32_t hacc[2][8][2];
#pragma unroll
    for (int i = 0; i < 2; i++)
#pragma unroll
        for (int j = 0; j < 8; j++) { hacc[i][j][0] = 0u; hacc[i][j][1] = 0u; }

    load_chunk(a_sm[0], b_sm[0], Abase, Bbase, 0, t); cp_commit();
    load_chunk(a_sm[1], b_sm[1], Abase, Bbase, 1, t); cp_commit();

#pragma unroll
    for (int c = 0; c < NCHUNKS; c++) {
        int stage = c % STAGES;
        if (c < NCHUNKS - 1) {
            asm volatile("cp.async.wait_group 1;" ::: "memory");
        } else {
            asm volatile("cp.async.wait_group 0;" ::: "memory");
        }
        __syncthreads();
        if (c + 2 < NCHUNKS) {
            int ns = (c + 2) % STAGES;
            load_chunk(a_sm[ns], b_sm[ns], Abase, Bbase, c + 2, t);
            cp_commit();
        }

        uint32_t ab = a_sm[stage], bb = b_sm[stage];
#pragma unroll
        for (int s = 0; s < 4; s++) {
            uint32_t kb0 = (uint32_t)(s * 32);
            uint32_t afrag[2][4], bfrag[4][4];
#pragma unroll
            for (int mi = 0; mi < 2; mi++)
                ldmx4(afrag[mi], ab + aRow[mi] + ((aKb + kb0) ^ aX));
#pragma unroll
            for (int j = 0; j < 4; j++)
                ldmx4(bfrag[j], bb + bRow[j] + ((bKb + kb0) ^ bX));
#pragma unroll
            for (int mi = 0; mi < 2; mi++)
#pragma unroll
                for (int j = 0; j < 4; j++) {
                    mma16816h(hacc[mi][2 * j],     afrag[mi], &bfrag[j][0]);
                    mma16816h(hacc[mi][2 * j + 1], afrag[mi], &bfrag[j][2]);
                }
        }
    }

    if (!LOGITS) {
#pragma unroll
        for (int mi = 0; mi < 2; mi++) {
            size_t r0 = row0 + mwarp0 + mi * 16 + (lane >> 2);
#pragma unroll
            for (int nj = 0; nj < 8; nj++) {
                int col = colc + nwarp0 + nj * 8 + (lane & 3) * 2;
                uint32_t v0 = hacc[mi][nj][0];
                uint32_t v1 = hacc[mi][nj][1];
                if (RES) {
                    uint32_t u0 = *(const uint32_t*)(Res + r0 * 1024 + col);
                    uint32_t u1 = *(const uint32_t*)(Res + (r0 + 8) * 1024 + col);
                    __half2 a0 = __hadd2(*(__half2*)&v0, *(__half2*)&u0);
                    __half2 a1 = __hadd2(*(__half2*)&v1, *(__half2*)&u1);
                    v0 = *(uint32_t*)&a0;
                    v1 = *(uint32_t*)&a1;
                }
                *(uint32_t*)(D + r0 * 1024 + col)       = v0;
                *(uint32_t*)(D + (r0 + 8) * 1024 + col) = v1;
            }
        }
    } else {
        float a0 = 0.f, a1 = 0.f;
        int bidx = (int)(row0 >> 11);
#pragma unroll
        for (int mi = 0; mi < 2; mi++) {
            size_t r0 = row0 + mwarp0 + mi * 16 + (lane >> 2);
            int l0 = (int)(r0 & 2047);
#pragma unroll
            for (int nj = 0; nj < 8; nj++) {
                int col = colc + nwarp0 + nj * 8 + (lane & 3) * 2;
                uint32_t v0 = hacc[mi][nj][0];
                uint32_t v1 = hacc[mi][nj][1];
                uint32_t u0 = *(const uint32_t*)(Res + r0 * 1024 + col);
                uint32_t u1 = *(const uint32_t*)(Res + (r0 + 8) * 1024 + col);
                __half2 s0 = __hadd2(*(__half2*)&v0, *(__half2*)&u0);
                __half2 s1 = __hadd2(*(__half2*)&v1, *(__half2*)&u1);
                float2 f0 = __half22float2(s0);
                float2 f1 = __half22float2(s1);
                uint2 w0u = *(const uint2*)(g_wf16 + ((size_t)l0 * 1024 + col) * 2);
                uint2 w1u = *(const uint2*)(g_wf16 + ((size_t)(l0 + 8) * 1024 + col) * 2);
                float2 w00 = __half22float2(*(__half2*)&w0u.x);
                float2 w01 = __half22float2(*(__half2*)&w0u.y);
                float2 w10 = __half22float2(*(__half2*)&w1u.x);
                float2 w11 = __half22float2(*(__half2*)&w1u.y);
                a0 += f0.x * w00.x + f0.y * w01.x + f1.x * w10.x + f1.y * w11.x;
                a1 += f0.x * w00.y + f0.y * w01.y + f1.x * w10.y + f1.y * w11.y;
            }
        }
#pragma unroll
        for (int off = 16; off >= 1; off >>= 1) {
            a0 += __shfl_xor_sync(0xffffffffu, a0, off);
            a1 += __shfl_xor_sync(0xffffffffu, a1, off);
        }
        if (lane == 0) {
            atomicAdd(&g_logits[2 * bidx],     (double)a0);
            atomicAdd(&g_logits[2 * bidx + 1], (double)a1);
        }
    }
}

// ---------------------------------------------------------------------------
// 3) Attention on tensor cores (f16 in/out, f32 softmax accum).
//    Split commit groups: wait for q+k before S; defer v-wait past softmax.
// ---------------------------------------------------------------------------
#define ATT_WARPS 8
#define ATT_SMEM (ATT_WARPS * 3 * 4096)   // 96 KB
#define ROWSTRIDE_B (LSEQ * NHEAD * DHEAD * 2)  // batch-row stride in bytes

__global__ __launch_bounds__(256) void attn_kernel()
{
    extern __shared__ char asmem[];
    int t = threadIdx.x, w = t >> 5, lane = t & 31;
    uint32_t wbase = smem_to_u32(asmem) + w * 12288;
    uint32_t qsm = wbase, ksm = wbase + 4096, vsm = wbase + 8192;

    int pair = blockIdx.x * ATT_WARPS + w;
    int l = pair >> 4, n = pair & 15;
    size_t ebase = ((size_t)l * NHEAD + n) * DHEAD;
    const char* qg = (const char*)(g_qb + ebase);
    const char* kg = (const char*)(g_kb + ebase);
    const char* vg = (const char*)(g_vb + ebase);

    // group 1: q + k
#pragma unroll
    for (int i = 0; i < 8; i++) {
        int s = lane + 32 * i;
        int row = s >> 3, sub = s & 7;
        size_t go = (size_t)row * ROWSTRIDE_B + sub * 16;
        uint32_t so = SMEM_SWIZZLE_128B((uint32_t)(row * 128 + sub * 16));
        cp_async16(qsm + so, qg + go);
        cp_async16(ksm + so, kg + go);
    }
    cp_commit();
    // group 2: v
#pragma unroll
    for (int i = 0; i < 8; i++) {
        int s = lane + 32 * i;
        int row = s >> 3, sub = s & 7;
        size_t go = (size_t)row * ROWSTRIDE_B + sub * 16;
        uint32_t so = SMEM_SWIZZLE_128B((uint32_t)(row * 128 + sub * 16));
        cp_async16(vsm + so, vg + go);
    }
    cp_commit();
    asm volatile("cp.async.wait_group 1;" ::: "memory");   // q, k ready
    __syncwarp();

    int g8 = lane & 7, sel = lane >> 3;

    // ---- S = Q K^T ----
    float c[2][4][4];
#pragma unroll
    for (int mi = 0; mi < 2; mi++)
#pragma unroll
        for (int j = 0; j < 4; j++)
#pragma unroll
            for (int k = 0; k < 4; k++) c[mi][j][k] = 0.f;

#pragma unroll
    for (int kc = 0; kc < 4; kc++) {
        uint32_t kb = kc * 32;
        uint32_t af[2][4], bfr[2][4];
#pragma unroll
        for (int mi = 0; mi < 2; mi++) {
            int row = mi * 16 + g8 + (sel & 1) * 8;
            uint32_t off = row * 128 + ((kb + (sel >> 1) * 16) ^ ((row & 7) << 4));
            ldmx4(af[mi], qsm + off);
        }
#pragma unroll
        for (int nj2 = 0; nj2 < 2; nj2++) {
            int row = nj2 * 16 + g8 + (sel >> 1) * 8;
            uint32_t off = row * 128 + ((kb + (sel & 1) * 16) ^ ((row & 7) << 4));
            ldmx4(bfr[nj2], ksm + off);
        }
#pragma unroll
        for (int mi = 0; mi < 2; mi++)
#pragma unroll
            for (int nj2 = 0; nj2 < 2; nj2++) {
                mma16816f(c[mi][2 * nj2],     af[mi], &bfr[nj2][0]);
                mma16816f(c[mi][2 * nj2 + 1], af[mi], &bfr[nj2][2]);
            }
    }

    // ---- softmax ----
    float inv0[2], inv1[2];
#pragma unroll
    for (int mi = 0; mi < 2; mi++) {
        float m0 = -FLT_MAX, m1 = -FLT_MAX;
#pragma unroll
        for (int j = 0; j < 4; j++) {
#pragma unroll
            for (int k = 0; k < 4; k++) c[mi][j][k] *= 0.125f;
            m0 = fmaxf(m0, fmaxf(c[mi][j][0], c[mi][j][1]));
            m1 = fmaxf(m1, fmaxf(c[mi][j][2], c[mi][j][3]));
        }
        m0 = fmaxf(m0, __shfl_xor_sync(0xffffffffu, m0, 1));
        m0 = fmaxf(m0, __shfl_xor_sync(0xffffffffu, m0, 2));
        m1 = fmaxf(m1, __shfl_xor_sync(0xffffffffu, m1, 1));
        m1 = fmaxf(m1, __shfl_xor_sync(0xffffffffu, m1, 2));
        float s0 = 0.f, s1 = 0.f;
#pragma unroll
        for (int j = 0; j < 4; j++) {
            c[mi][j][0] = __expf(c[mi][j][0] - m0);
            c[mi][j][1] = __expf(c[mi][j][1] - m0);
            c[mi][j][2] = __expf(c[mi][j][2] - m1);
            c[mi][j][3] = __expf(c[mi][j][3] - m1);
            s0 += c[mi][j][0] + c[mi][j][1];
            s1 += c[mi][j][2] + c[mi][j][3];
        }
        s0 += __shfl_xor_sync(0xffffffffu, s0, 1);
        s0 += __shfl_xor_sync(0xffffffffu, s0, 2);
        s1 += __shfl_xor_sync(0xffffffffu, s1, 1);
        s1 += __shfl_xor_sync(0xffffffffu, s1, 2);
        inv0[mi] = 1.f / s0;
        inv1[mi] = 1.f / s1;
    }

    // ---- pack P ----
    uint32_t pf[2][2][4];
#pragma unroll
    for (int mi = 0; mi < 2; mi++)
#pragma unroll
        for (int kc = 0; kc < 2; kc++) {
            __half2 x0 = __floats2half2_rn(c[mi][2 * kc][0],     c[mi][2 * kc][1]);
            __half2 x1 = __floats2half2_rn(c[mi][2 * kc][2],     c[mi][2 * kc][3]);
            __half2 x2 = __floats2half2_rn(c[mi][2 * kc + 1][0], c[mi][2 * kc + 1][1]);
            __half2 x3 = __floats2half2_rn(c[mi][2 * kc + 1][2], c[mi][2 * kc + 1][3]);
            pf[mi][kc][0] = *(uint32_t*)&x0;
            pf[mi][kc][1] = *(uint32_t*)&x1;
            pf[mi][kc][2] = *(uint32_t*)&x2;
            pf[mi][kc][3] = *(uint32_t*)&x3;
        }

    // v ready
    asm volatile("cp.async.wait_group 0;" ::: "memory");
    __syncwarp();

    // ---- att = P V ----
    float cv[2][8][4];
#pragma unroll
    for (int mi = 0; mi < 2; mi++)
#pragma unroll
        for (int j = 0; j < 8; j++)
#pragma unroll
            for (int k = 0; k < 4; k++) cv[mi][j][k] = 0.f;

#pragma unroll
    for (int kc = 0; kc < 2; kc++) {
#pragma unroll
        for (int dj2 = 0; dj2 < 4; dj2++) {
            int row = kc * 16 + g8 + (sel & 1) * 8;
            uint32_t colb = dj2 * 32 + (sel >> 1) * 16;
            uint32_t off = row * 128 + (colb ^ ((row & 7) << 4));
            uint32_t bv[4];
            ldmx4t(bv, vsm + off);
#pragma unroll
            for (int mi = 0; mi < 2; mi++) {
                mma16816f(cv[mi][2 * dj2],     pf[mi][kc], &bv[0]);
                mma16816f(cv[mi][2 * dj2 + 1], pf[mi][kc], &bv[2]);
            }
        }
    }

    // ---- normalize + store (in place into g_qb) ----
    int r = lane >> 2, cq = (lane & 3) * 2;
#pragma unroll
    for (int mi = 0; mi < 2; mi++) {
        int i0 = mi * 16 + r;
        __half* o0 = g_qb + ebase + (size_t)i0 * (LSEQ * NHEAD * DHEAD);
        __half* o1 = o0 + (size_t)8 * (LSEQ * NHEAD * DHEAD);
#pragma unroll
        for (int dj = 0; dj < 8; dj++) {
            int col = dj * 8 + cq;
            __half2 h0 = __floats2half2_rn(cv[mi][dj][0] * inv0[mi],
                                           cv[mi][dj][1] * inv0[mi]);
            __half2 h1 = __floats2half2_rn(cv[mi][dj][2] * inv1[mi],
                                           cv[mi][dj][3] * inv1[mi]);
            *(uint32_t*)(o0 + col) = *(uint32_t*)&h0;
            *(uint32_t*)(o1 + col) = *(uint32_t*)&h1;
        }
    }
}

// ---------------------------------------------------------------------------
// 4) Loss
// ---------------------------------------------------------------------------
__global__ void loss_kernel(const int* __restrict__ y,
                            const float* __restrict__ bf,
                            float* __restrict__ out)
{
    if (threadIdx.x != 0 || blockIdx.x != 0) return;
    double s = 0.0;
    double b0 = (double)bf[0], b1 = (double)bf[1];
    for (int b = 0; b < BATCH; b++) {
        double l0 = g_logits[2 * b]     + b0;
        double l1 = g_logits[2 * b + 1] + b1;
        double m  = l0 > l1 ? l0 : l1;
        double lse = m + log(exp(l0 - m) + exp(l1 - m));
        double lp  = (y[b] == 0 ? l0 : l1) - lse;
        s += lp;
    }
    out[0] = (float)(-s / (double)BATCH);
}

// ---------------------------------------------------------------------------
// Launch
// ---------------------------------------------------------------------------
extern "C" void kernel_launch(void* const* d_in, const int* in_sizes, int n_in,
                              void* d_out, int out_size)
{
    const int*   x     = (const int*)d_in[0];
    const int*   y     = (const int*)d_in[1];
    const float* emb   = (const float*)d_in[2];
    const float* Wq    = (const float*)d_in[3];
    const float* Wkv   = (const float*)d_in[4];
    const float* Wo    = (const float*)d_in[5];
    const float* Wf    = (const float*)d_in[6];
    const float* bf    = (const float*)d_in[7];
    float* out = (float*)d_out;

    __half *p_hb, *p_qb, *p_kb, *p_vb, *p_wqkv, *p_wo;
    cudaGetSymbolAddress((void**)&p_hb,   g_hb);
    cudaGetSymbolAddress((void**)&p_qb,   g_qb);
    cudaGetSymbolAddress((void**)&p_kb,   g_kb);
    cudaGetSymbolAddress((void**)&p_vb,   g_vb);
    cudaGetSymbolAddress((void**)&p_wqkv, g_wqkv);
    cudaGetSymbolAddress((void**)&p_wo,   g_wo);

    cudaFuncSetAttribute((void*)gemm_f16_kernel<false, false>,
                         cudaFuncAttributeMaxDynamicSharedMemorySize, GEMM_SMEM);
    cudaFuncSetAttribute((void*)gemm_f16_kernel<true, true>,
                         cudaFuncAttributeMaxDynamicSharedMemorySize, GEMM_SMEM);
    cudaFuncSetAttribute(attn_kernel,
                         cudaFuncAttributeMaxDynamicSharedMemorySize, ATT_SMEM);

    // 1) merged prologue: transposes + logits zero + Wf f16 + gather
    prep_kernel<<<PREP_BLOCKS, 256>>>(x, emb, Wq, Wkv, Wo, Wf, p_wqkv, p_wo);

    // 2) fused QKV projection: one GEMM, N = 3072
    {
        int nx = 3 * EDIM / NT;              // 24
        gemm_f16_kernel<false, false><<<dim3(nx * (ROWS / MT), 1), 256, GEMM_SMEM>>>(
            p_hb, p_wqkv, nullptr, p_qb, p_kb, p_vb, nx);
    }

    // 3) attention (tensor cores; in place: g_qb <- att)
    attn_kernel<<<LSEQ * NHEAD / ATT_WARPS, 256, ATT_SMEM>>>();

    // 4) out = h + att @ Wo, fused with logits = out . Wf  (no g_ob)
    {
        int nx = EDIM / NT;                  // 8
        gemm_f16_kernel<true, true><<<dim3(nx * (ROWS / MT), 1), 256, GEMM_SMEM>>>(
            p_qb, p_wo, p_hb, nullptr, nullptr, nullptr, nx);
    }

    // 5) loss
    loss_kernel<<<1, 32>>>(y, bf, out);
}